// round 9
// baseline (speedup 1.0000x reference)
#include <cuda_runtime.h>
#include <cuda_fp16.h>
#include <stdint.h>

#define S    4096
#define MDIM 1024
#define E    8
#define CAP  1024
#define BM   128
#define BN   256
#define BK   32
#define NKC  (MDIM / BK)   // 32

// ---------------- scratch (device globals; no allocation) ----------------
__device__ int    g_e0[S];
__device__ float  g_gate[S];
__device__ float  g_me_part[512 * E];
__device__ int    g_tok[E * CAP];
__device__ int    g_ne[E];
__device__ __half g_xh[S * MDIM];                 // x rounded to fp16
__device__ __half g_weh[E * MDIM * MDIM];         // we hi (fp16), [e][k][n]
__device__ __half g_wel[E * MDIM * MDIM];         // we lo (fp16)

__device__ __forceinline__ uint32_t smem_u32(const void* p) {
    uint32_t a;
    asm("{ .reg .u64 t; cvta.to.shared.u64 t, %1; cvt.u32.u64 %0, t; }" : "=r"(a) : "l"(p));
    return a;
}
__device__ __forceinline__ void cp_async16(uint32_t dst, const void* src, uint32_t bytes) {
    asm volatile("cp.async.cg.shared.global [%0], [%1], 16, %2;"
                 :: "r"(dst), "l"(src), "r"(bytes) : "memory");
}
#define CP_COMMIT() asm volatile("cp.async.commit_group;" ::: "memory")
#define CP_WAIT(n)  asm volatile("cp.async.wait_group %0;" :: "n"(n) : "memory")

__device__ __forceinline__ void ldmat_x4(uint32_t* r, uint32_t addr) {
    asm volatile("ldmatrix.sync.aligned.m8n8.x4.shared.b16 {%0,%1,%2,%3}, [%4];"
                 : "=r"(r[0]), "=r"(r[1]), "=r"(r[2]), "=r"(r[3]) : "r"(addr));
}
__device__ __forceinline__ void ldmat_x4_t(uint32_t* r, uint32_t addr) {
    asm volatile("ldmatrix.sync.aligned.m8n8.x4.trans.shared.b16 {%0,%1,%2,%3}, [%4];"
                 : "=r"(r[0]), "=r"(r[1]), "=r"(r[2]), "=r"(r[3]) : "r"(addr));
}
__device__ __forceinline__ void mma16816(float* c, const uint32_t* a, uint32_t b0, uint32_t b1) {
    asm volatile("mma.sync.aligned.m16n8k16.row.col.f32.f16.f16.f32 "
                 "{%0,%1,%2,%3}, {%4,%5,%6,%7}, {%8,%9}, {%0,%1,%2,%3};"
                 : "+f"(c[0]), "+f"(c[1]), "+f"(c[2]), "+f"(c[3])
                 : "r"(a[0]), "r"(a[1]), "r"(a[2]), "r"(a[3]), "r"(b0), "r"(b1));
}

// ---------------- kernel 1: gating + fused x->fp16 + me partials ----------------
__global__ void __launch_bounds__(256) gate_kernel(const float* __restrict__ x,
                                                   const float* __restrict__ wg) {
    __shared__ float wgs[E * MDIM];
    __shared__ float s_pr[8][E];
    int tid = threadIdx.x;
    for (int i = tid; i < E * MDIM / 4; i += 256)
        ((float4*)wgs)[i] = ((const float4*)wg)[i];
    __syncthreads();

    int warp = tid >> 5, lane = tid & 31;
    int s = blockIdx.x * 8 + warp;
    const float4* xr = (const float4*)(x + (size_t)s * MDIM);
    __half2* xh = (__half2*)(g_xh + (size_t)s * MDIM);
    float acc[E];
#pragma unroll
    for (int e = 0; e < E; e++) acc[e] = 0.f;
#pragma unroll
    for (int it = 0; it < MDIM / 128; it++) {
        int k4 = it * 32 + lane;
        float4 xv = xr[k4];
        xh[k4 * 2 + 0] = __halves2half2(__float2half_rn(xv.x), __float2half_rn(xv.y));
        xh[k4 * 2 + 1] = __halves2half2(__float2half_rn(xv.z), __float2half_rn(xv.w));
#pragma unroll
        for (int e = 0; e < E; e++) {
            float4 wv = ((const float4*)(wgs + e * MDIM))[k4];
            acc[e] += xv.x * wv.x + xv.y * wv.y + xv.z * wv.z + xv.w * wv.w;
        }
    }
#pragma unroll
    for (int e = 0; e < E; e++) {
#pragma unroll
        for (int off = 16; off; off >>= 1)
            acc[e] += __shfl_xor_sync(0xffffffffu, acc[e], off);
    }
    if (lane == 0) {
        float mx = acc[0]; int ei = 0;
#pragma unroll
        for (int e = 1; e < E; e++) if (acc[e] > mx) { mx = acc[e]; ei = e; }
        float ex[E]; float sum = 0.f;
#pragma unroll
        for (int e = 0; e < E; e++) { ex[e] = expf(acc[e] - mx); sum += ex[e]; }
        float inv = 1.f / sum;
#pragma unroll
        for (int e = 0; e < E; e++) s_pr[warp][e] = ex[e] * inv;
        g_e0[s]   = ei;
        g_gate[s] = ex[ei] * inv;
    }
    __syncthreads();
    if (tid < E) {
        float m = 0.f;
#pragma unroll
        for (int w = 0; w < 8; w++) m += s_pr[w][tid];
        g_me_part[blockIdx.x * E + tid] = m;
    }
}

// ---------------- kernel 2: ordered prefix scan + loss ----------------
__global__ void __launch_bounds__(256) scan_kernel(float* __restrict__ d_out,
                                                   long long out_size) {
    const int T = 256, CH = S / T;  // 16
    __shared__ int   cnt[T][E];
    __shared__ float s_me[32][E];
    __shared__ int   tot[E];
    int tid = threadIdx.x;

    int e0l[CH];
    {
        const int4* p = (const int4*)(g_e0 + tid * CH);
#pragma unroll
        for (int q = 0; q < CH / 4; q++) {
            int4 v = p[q];
            e0l[q * 4 + 0] = v.x; e0l[q * 4 + 1] = v.y;
            e0l[q * 4 + 2] = v.z; e0l[q * 4 + 3] = v.w;
        }
    }
    int c[E];
#pragma unroll
    for (int e = 0; e < E; e++) c[e] = 0;
#pragma unroll
    for (int i = 0; i < CH; i++) c[e0l[i]]++;
#pragma unroll
    for (int e = 0; e < E; e++) cnt[tid][e] = c[e];

    {
        int e = tid & 7, grp = tid >> 3;
        float m = 0.f;
#pragma unroll
        for (int j = 0; j < 16; j++) m += g_me_part[(grp * 16 + j) * E + e];
        s_me[grp][e] = m;
    }
    __syncthreads();
    for (int stride = 16; stride; stride >>= 1) {
        if (tid < stride * E) {
            int e = tid & 7, grp = tid >> 3;
            s_me[grp][e] += s_me[grp + stride][e];
        }
        __syncthreads();
    }

    if (tid < E) {
        int run = 0;
        for (int t = 0; t < T; t++) { int v = cnt[t][tid]; cnt[t][tid] = run; run += v; }
        tot[tid] = run;
        g_ne[tid] = run < CAP ? run : CAP;
    }
    __syncthreads();
    int off[E];
#pragma unroll
    for (int e = 0; e < E; e++) off[e] = cnt[tid][e];
    int base_s = tid * CH;
#pragma unroll
    for (int i = 0; i < CH; i++) {
        int e = e0l[i];
        int loc = off[e]++;
        if (loc < CAP) g_tok[e * CAP + loc] = base_s + i;
    }
    if (tid == 0 && out_size > (long long)S * MDIM) {
        float loss = 0.f;
#pragma unroll
        for (int e = 0; e < E; e++) loss += s_me[0][e] * (float)tot[e];
        loss *= (float)E / ((float)S * (float)S);
        d_out[(long long)S * MDIM] = loss;
    }
}

// ---------------- prep: we fp32 -> fp16 hi/lo ----------------
__global__ void __launch_bounds__(256) split_we_kernel(const float* __restrict__ we) {
    size_t i = (size_t)blockIdx.x * 256 + threadIdx.x;
    float4 v = ((const float4*)we)[i];
    __half h0 = __float2half_rn(v.x), h1 = __float2half_rn(v.y);
    __half h2 = __float2half_rn(v.z), h3 = __float2half_rn(v.w);
    __half2* oh = (__half2*)g_weh + i * 2;
    __half2* ol = (__half2*)g_wel + i * 2;
    oh[0] = __halves2half2(h0, h1);
    oh[1] = __halves2half2(h2, h3);
    ol[0] = __halves2half2(__float2half_rn(v.x - __half2float(h0)),
                           __float2half_rn(v.y - __half2float(h1)));
    ol[1] = __halves2half2(__float2half_rn(v.z - __half2float(h2)),
                           __float2half_rn(v.w - __half2float(h3)));
}

// ---------------- kernel 3: grouped GEMM, 128x256x32, 64x64 warp tiles ----------------
#define A_ROWB 80
#define B_ROWB 528
#define A_TILE (BM * A_ROWB)            // 10240
#define B_TILE (BK * B_ROWB)            // 16896
#define STG_AH 0
#define STG_BH (A_TILE)
#define STG_BL (A_TILE + B_TILE)
#define STG_SZ (A_TILE + 2 * B_TILE)    // 44032
#define STAGES 4
#define SMEM_BYTES (STAGES * STG_SZ)    // 176128

__global__ void __launch_bounds__(256) moe_gemm_mma(float* __restrict__ out) {
    int e  = blockIdx.z;
    int ne = g_ne[e];
    int r0 = blockIdx.y * BM;
    if (r0 >= ne) return;
    int n0 = blockIdx.x * BN;

    extern __shared__ __align__(16) char sm[];
    uint32_t sb = smem_u32(sm);
    __shared__ int   s_toks[BM];
    __shared__ float s_gts[BM];

    int tid = threadIdx.x;
    int wid = tid >> 5, lane = tid & 31;

    if (tid < BM) {
        int r = r0 + tid;
        int t = (r < ne) ? g_tok[e * CAP + r] : -1;
        s_toks[tid] = t;
        s_gts[tid]  = (t >= 0) ? g_gate[t] : 0.f;
    }
    __syncthreads();

    // A load: 128 rows x 64B; thread -> (row=tid>>1, 2 chunks of 16B)
    int arow = tid >> 1, aseg = tid & 1;
    int atok = s_toks[arow];
    const char* axh = (const char*)(g_xh + ((atok >= 0 ? (size_t)atok : 0) * MDIM)) + aseg * 32;
    uint32_t abytes = (atok >= 0) ? 16u : 0u;
    uint32_t adst = arow * A_ROWB + aseg * 32;

    // B load: 32 rows x 512B per plane; thread -> (row=tid>>3, 4 chunks 128B apart)
    int brow = tid >> 3, bc = tid & 7;
    const char* bwh = (const char*)(g_weh + ((size_t)e << 20) + (size_t)brow * MDIM + n0) + bc * 16;
    const char* bwl = (const char*)(g_wel + ((size_t)e << 20) + (size_t)brow * MDIM + n0) + bc * 16;
    uint32_t bdst = brow * B_ROWB + bc * 16;
    const size_t bkstep = (size_t)BK * MDIM * 2;

    auto issue = [&](int kc, int st) {
        uint32_t so = sb + st * STG_SZ;
        size_t akoff = (size_t)kc * BK * 2;
        cp_async16(so + STG_AH + adst,      axh + akoff,      abytes);
        cp_async16(so + STG_AH + adst + 16, axh + akoff + 16, abytes);
        size_t bko = (size_t)kc * bkstep;
#pragma unroll
        for (int j = 0; j < 4; j++) {
            cp_async16(so + STG_BH + bdst + j * 128, bwh + bko + j * 128, 16u);
            cp_async16(so + STG_BL + bdst + j * 128, bwl + bko + j * 128, 16u);
        }
        CP_COMMIT();
    };

    int wm = wid & 1, wn = wid >> 1;   // 8 warps: 2m x 4n, warp tile 64m x 64n
    float acc[4][8][4];
#pragma unroll
    for (int a = 0; a < 4; a++)
#pragma unroll
        for (int b = 0; b < 8; b++)
#pragma unroll
            for (int c2 = 0; c2 < 4; c2++) acc[a][b][c2] = 0.f;

    issue(0, 0);
    issue(1, 1);
    issue(2, 2);

    int st = 0;
    for (int i = 0; i < NKC; i++) {
        if (i + 1 < NKC) { CP_WAIT(2); } else { CP_WAIT(0); }
        __syncthreads();
        if (i + 3 < NKC) {
            int nst = st + 3; if (nst >= STAGES) nst -= STAGES;
            issue(i + 3, nst);
        }

        uint32_t so  = sb + st * STG_SZ;
        uint32_t AHs = so + STG_AH;
        uint32_t BHs = so + STG_BH;
        uint32_t BLs = so + STG_BL;

#pragma unroll
        for (int ks = 0; ks < 2; ks++) {
            uint32_t ah[4][4], bh[4][4], bl[4][4];
            uint32_t aoff = ks * 32 + 16 * (lane >> 4);
#pragma unroll
            for (int mt = 0; mt < 4; mt++) {
                uint32_t row = wm * 64 + mt * 16 + (lane & 15);
                ldmat_x4(ah[mt], AHs + row * A_ROWB + aoff);
            }
            uint32_t brow16 = ks * 16 + (lane & 7) + 8 * ((lane >> 3) & 1);
#pragma unroll
            for (int nh = 0; nh < 4; nh++) {
                uint32_t boff = brow16 * B_ROWB + wn * 128 + nh * 32 + 16 * (lane >> 4);
                ldmat_x4_t(bh[nh], BHs + boff);
                ldmat_x4_t(bl[nh], BLs + boff);
            }
            // hi pass: 32 independent accumulators before any repeat
#pragma unroll
            for (int mt = 0; mt < 4; mt++) {
#pragma unroll
                for (int ns = 0; ns < 8; ns++) {
                    uint32_t b0 = bh[ns >> 1][(ns & 1) * 2], b1 = bh[ns >> 1][(ns & 1) * 2 + 1];
                    mma16816(acc[mt][ns], ah[mt], b0, b1);
                }
            }
            // lo pass
#pragma unroll
            for (int mt = 0; mt < 4; mt++) {
#pragma unroll
                for (int ns = 0; ns < 8; ns++) {
                    uint32_t b0 = bl[ns >> 1][(ns & 1) * 2], b1 = bl[ns >> 1][(ns & 1) * 2 + 1];
                    mma16816(acc[mt][ns], ah[mt], b0, b1);
                }
            }
        }
        st++; if (st >= STAGES) st = 0;
    }

    // epilogue
#pragma unroll
    for (int mt = 0; mt < 4; mt++) {
#pragma unroll
        for (int half = 0; half < 2; half++) {
            int m = wm * 64 + mt * 16 + half * 8 + (lane >> 2);
            if (r0 + m < ne) {
                int   t = s_toks[m];
                float g = s_gts[m];
                float* orow = out + (size_t)t * MDIM + n0 + wn * 64 + (lane & 3) * 2;
#pragma unroll
                for (int ns = 0; ns < 8; ns++) {
                    float2 v;
                    v.x = g * acc[mt][ns][half * 2 + 0];
                    v.y = g * acc[mt][ns][half * 2 + 1];
                    *(float2*)(orow + ns * 8) = v;
                }
            }
        }
    }
}

// ---------------- launcher ----------------
extern "C" void kernel_launch(void* const* d_in, const int* in_sizes, int n_in,
                              void* d_out, int out_size) {
    const float* x  = (const float*)d_in[0];
    const float* wg = (const float*)d_in[1];
    const float* we = (const float*)d_in[2];
    float* out = (float*)d_out;

    static cudaStream_t s2 = nullptr;
    static cudaEvent_t evFork = nullptr, evJoin = nullptr;
    if (s2 == nullptr) {
        cudaStreamCreateWithFlags(&s2, cudaStreamNonBlocking);
        cudaEventCreateWithFlags(&evFork, cudaEventDisableTiming);
        cudaEventCreateWithFlags(&evJoin, cudaEventDisableTiming);
    }

    cudaEventRecord(evFork, 0);
    cudaStreamWaitEvent(s2, evFork, 0);

    cudaMemsetAsync(d_out, 0, sizeof(float) * (size_t)S * MDIM, s2);
    split_we_kernel<<<(E * MDIM * MDIM / 4) / 256, 256, 0, s2>>>(we);

    gate_kernel<<<S / 8, 256>>>(x, wg);
    scan_kernel<<<1, 256>>>(out, (long long)out_size);

    cudaEventRecord(evJoin, s2);
    cudaStreamWaitEvent(0, evJoin, 0);

    cudaFuncSetAttribute(moe_gemm_mma, cudaFuncAttributeMaxDynamicSharedMemorySize, SMEM_BYTES);
    dim3 grid(MDIM / BN, CAP / BM, E);
    moe_gemm_mma<<<grid, 256, SMEM_BYTES>>>(out);
}

// round 10
// speedup vs baseline: 1.0189x; 1.0189x over previous
#include <cuda_runtime.h>
#include <cuda_fp16.h>
#include <stdint.h>

#define S    4096
#define MDIM 1024
#define E    8
#define CAP  1024
#define BM   128
#define BN   128
#define BK   32
#define NKC  (MDIM / BK)   // 32

// ---------------- scratch (device globals; no allocation) ----------------
__device__ int    g_e0[S];
__device__ float  g_gate[S];
__device__ float  g_me_part[512 * E];
__device__ int    g_tok[E * CAP];
__device__ int    g_ne[E];
__device__ __half g_xh[S * MDIM];                 // x rounded to fp16
__device__ __half g_weh[E * MDIM * MDIM];         // we hi (fp16), [e][k][n]
__device__ __half g_wel[E * MDIM * MDIM];         // we lo (fp16)

__device__ __forceinline__ uint32_t smem_u32(const void* p) {
    uint32_t a;
    asm("{ .reg .u64 t; cvta.to.shared.u64 t, %1; cvt.u32.u64 %0, t; }" : "=r"(a) : "l"(p));
    return a;
}
__device__ __forceinline__ void cp_async16(uint32_t dst, const void* src, uint32_t bytes) {
    asm volatile("cp.async.cg.shared.global [%0], [%1], 16, %2;"
                 :: "r"(dst), "l"(src), "r"(bytes) : "memory");
}
#define CP_COMMIT() asm volatile("cp.async.commit_group;" ::: "memory")
#define CP_WAIT(n)  asm volatile("cp.async.wait_group %0;" :: "n"(n) : "memory")

__device__ __forceinline__ void ldmat_x4(uint32_t* r, uint32_t addr) {
    asm volatile("ldmatrix.sync.aligned.m8n8.x4.shared.b16 {%0,%1,%2,%3}, [%4];"
                 : "=r"(r[0]), "=r"(r[1]), "=r"(r[2]), "=r"(r[3]) : "r"(addr));
}
__device__ __forceinline__ void ldmat_x4_t(uint32_t* r, uint32_t addr) {
    asm volatile("ldmatrix.sync.aligned.m8n8.x4.trans.shared.b16 {%0,%1,%2,%3}, [%4];"
                 : "=r"(r[0]), "=r"(r[1]), "=r"(r[2]), "=r"(r[3]) : "r"(addr));
}
__device__ __forceinline__ void mma16816(float* c, const uint32_t* a, uint32_t b0, uint32_t b1) {
    asm volatile("mma.sync.aligned.m16n8k16.row.col.f32.f16.f16.f32 "
                 "{%0,%1,%2,%3}, {%4,%5,%6,%7}, {%8,%9}, {%0,%1,%2,%3};"
                 : "+f"(c[0]), "+f"(c[1]), "+f"(c[2]), "+f"(c[3])
                 : "r"(a[0]), "r"(a[1]), "r"(a[2]), "r"(a[3]), "r"(b0), "r"(b1));
}

// ---------------- kernel 1: gating + fused x->fp16 + me partials ----------------
// All 8 x-float4 loads hoisted up front (MLP=8), then 8x8 FMA block vs smem.
__global__ void __launch_bounds__(256) gate_kernel(const float* __restrict__ x,
                                                   const float* __restrict__ wg) {
    __shared__ float wgs[E * MDIM];
    __shared__ float s_pr[8][E];
    int tid = threadIdx.x;
    for (int i = tid; i < E * MDIM / 4; i += 256)
        ((float4*)wgs)[i] = ((const float4*)wg)[i];

    int warp = tid >> 5, lane = tid & 31;
    int s = blockIdx.x * 8 + warp;
    const float4* xr = (const float4*)(x + (size_t)s * MDIM);

    // hoisted loads: 8 independent float4s in flight
    float4 xv[8];
#pragma unroll
    for (int it = 0; it < 8; it++) xv[it] = xr[it * 32 + lane];

    // fused split to fp16 (stores don't block)
    __half2* xh = (__half2*)(g_xh + (size_t)s * MDIM);
#pragma unroll
    for (int it = 0; it < 8; it++) {
        int k4 = it * 32 + lane;
        xh[k4 * 2 + 0] = __halves2half2(__float2half_rn(xv[it].x), __float2half_rn(xv[it].y));
        xh[k4 * 2 + 1] = __halves2half2(__float2half_rn(xv[it].z), __float2half_rn(xv[it].w));
    }
    __syncthreads();

    float acc[E];
#pragma unroll
    for (int e = 0; e < E; e++) acc[e] = 0.f;
#pragma unroll
    for (int it = 0; it < 8; it++) {
        int k4 = it * 32 + lane;
#pragma unroll
        for (int e = 0; e < E; e++) {
            float4 wv = ((const float4*)(wgs + e * MDIM))[k4];
            acc[e] += xv[it].x * wv.x + xv[it].y * wv.y + xv[it].z * wv.z + xv[it].w * wv.w;
        }
    }
#pragma unroll
    for (int e = 0; e < E; e++) {
#pragma unroll
        for (int off = 16; off; off >>= 1)
            acc[e] += __shfl_xor_sync(0xffffffffu, acc[e], off);
    }
    if (lane == 0) {
        float mx = acc[0]; int ei = 0;
#pragma unroll
        for (int e = 1; e < E; e++) if (acc[e] > mx) { mx = acc[e]; ei = e; }
        float ex[E]; float sum = 0.f;
#pragma unroll
        for (int e = 0; e < E; e++) { ex[e] = expf(acc[e] - mx); sum += ex[e]; }
        float inv = 1.f / sum;
#pragma unroll
        for (int e = 0; e < E; e++) s_pr[warp][e] = ex[e] * inv;
        g_e0[s]   = ei;
        g_gate[s] = ex[ei] * inv;
    }
    __syncthreads();
    if (tid < E) {
        float m = 0.f;
#pragma unroll
        for (int w = 0; w < 8; w++) m += s_pr[w][tid];
        g_me_part[blockIdx.x * E + tid] = m;
    }
}

// ---------------- kernel 2: ordered prefix scan + loss ----------------
__global__ void __launch_bounds__(256) scan_kernel(float* __restrict__ d_out,
                                                   long long out_size) {
    const int T = 256, CH = S / T;  // 16
    __shared__ int   cnt[T][E];
    __shared__ float s_me[32][E];
    __shared__ int   tot[E];
    int tid = threadIdx.x;

    int e0l[CH];
    {
        const int4* p = (const int4*)(g_e0 + tid * CH);
#pragma unroll
        for (int q = 0; q < CH / 4; q++) {
            int4 v = p[q];
            e0l[q * 4 + 0] = v.x; e0l[q * 4 + 1] = v.y;
            e0l[q * 4 + 2] = v.z; e0l[q * 4 + 3] = v.w;
        }
    }
    int c[E];
#pragma unroll
    for (int e = 0; e < E; e++) c[e] = 0;
#pragma unroll
    for (int i = 0; i < CH; i++) c[e0l[i]]++;
#pragma unroll
    for (int e = 0; e < E; e++) cnt[tid][e] = c[e];

    {
        int e = tid & 7, grp = tid >> 3;
        float m = 0.f;
#pragma unroll
        for (int j = 0; j < 16; j++) m += g_me_part[(grp * 16 + j) * E + e];
        s_me[grp][e] = m;
    }
    __syncthreads();
    for (int stride = 16; stride; stride >>= 1) {
        if (tid < stride * E) {
            int e = tid & 7, grp = tid >> 3;
            s_me[grp][e] += s_me[grp + stride][e];
        }
        __syncthreads();
    }

    if (tid < E) {
        int run = 0;
        for (int t = 0; t < T; t++) { int v = cnt[t][tid]; cnt[t][tid] = run; run += v; }
        tot[tid] = run;
        g_ne[tid] = run < CAP ? run : CAP;
    }
    __syncthreads();
    int off[E];
#pragma unroll
    for (int e = 0; e < E; e++) off[e] = cnt[tid][e];
    int base_s = tid * CH;
#pragma unroll
    for (int i = 0; i < CH; i++) {
        int e = e0l[i];
        int loc = off[e]++;
        if (loc < CAP) g_tok[e * CAP + loc] = base_s + i;
    }
    if (tid == 0 && out_size > (long long)S * MDIM) {
        float loss = 0.f;
#pragma unroll
        for (int e = 0; e < E; e++) loss += s_me[0][e] * (float)tot[e];
        loss *= (float)E / ((float)S * (float)S);
        d_out[(long long)S * MDIM] = loss;
    }
}

// ---------------- prep: we fp32 -> fp16 hi/lo ----------------
__global__ void __launch_bounds__(256) split_we_kernel(const float* __restrict__ we) {
    size_t i = (size_t)blockIdx.x * 256 + threadIdx.x;
    float4 v = ((const float4*)we)[i];
    __half h0 = __float2half_rn(v.x), h1 = __float2half_rn(v.y);
    __half h2 = __float2half_rn(v.z), h3 = __float2half_rn(v.w);
    __half2* oh = (__half2*)g_weh + i * 2;
    __half2* ol = (__half2*)g_wel + i * 2;
    oh[0] = __halves2half2(h0, h1);
    oh[1] = __halves2half2(h2, h3);
    ol[0] = __halves2half2(__float2half_rn(v.x - __half2float(h0)),
                           __float2half_rn(v.y - __half2float(h1)));
    ol[1] = __halves2half2(__float2half_rn(v.z - __half2float(h2)),
                           __float2half_rn(v.w - __half2float(h3)));
}

// ---------------- kernel 3: grouped GEMM, 128x128x32, 256thr, 2 CTA/SM ----------------
#define A_ROWB 80
#define B_ROWB 272
#define A_TILE (BM * A_ROWB)            // 10240
#define B_TILE (BK * B_ROWB)            // 8704
#define STG_AH 0
#define STG_BH (A_TILE)
#define STG_BL (A_TILE + B_TILE)
#define STG_SZ (A_TILE + 2 * B_TILE)    // 27648
#define STAGES 4
#define SMEM_BYTES (STAGES * STG_SZ)    // 110592

__global__ void __launch_bounds__(256, 2) moe_gemm_mma(float* __restrict__ out) {
    int e  = blockIdx.z;
    int ne = g_ne[e];
    int r0 = blockIdx.y * BM;
    if (r0 >= ne) return;
    int n0 = blockIdx.x * BN;

    extern __shared__ __align__(16) char sm[];
    uint32_t sb = smem_u32(sm);
    __shared__ int   s_toks[BM];
    __shared__ float s_gts[BM];

    int tid = threadIdx.x;
    int wid = tid >> 5, lane = tid & 31;

    if (tid < BM) {
        int r = r0 + tid;
        int t = (r < ne) ? g_tok[e * CAP + r] : -1;
        s_toks[tid] = t;
        s_gts[tid]  = (t >= 0) ? g_gate[t] : 0.f;
    }
    __syncthreads();

    // A load: 128 rows x 64B; thread -> (row=tid>>1, 2 chunks of 16B)
    int arow = tid >> 1, aseg = tid & 1;
    int atok = s_toks[arow];
    const char* axh = (const char*)(g_xh + ((atok >= 0 ? (size_t)atok : 0) * MDIM)) + aseg * 32;
    uint32_t abytes = (atok >= 0) ? 16u : 0u;
    uint32_t adst = arow * A_ROWB + aseg * 32;

    // B load: 32 rows x 256B per plane; thread -> (row=tid>>3, 2 chunks 128B apart)
    int brow = tid >> 3, bc = tid & 7;
    const char* bwh = (const char*)(g_weh + ((size_t)e << 20) + (size_t)brow * MDIM + n0) + bc * 16;
    const char* bwl = (const char*)(g_wel + ((size_t)e << 20) + (size_t)brow * MDIM + n0) + bc * 16;
    uint32_t bdst = brow * B_ROWB + bc * 16;
    const size_t bkstep = (size_t)BK * MDIM * 2;

    auto issue = [&](int kc, int st) {
        uint32_t so = sb + st * STG_SZ;
        size_t akoff = (size_t)kc * BK * 2;
        cp_async16(so + STG_AH + adst,      axh + akoff,      abytes);
        cp_async16(so + STG_AH + adst + 16, axh + akoff + 16, abytes);
        size_t bko = (size_t)kc * bkstep;
#pragma unroll
        for (int j = 0; j < 2; j++) {
            cp_async16(so + STG_BH + bdst + j * 128, bwh + bko + j * 128, 16u);
            cp_async16(so + STG_BL + bdst + j * 128, bwl + bko + j * 128, 16u);
        }
        CP_COMMIT();
    };

    int wm = wid & 3, wn = wid >> 2;   // 8 warps: 4m x 2n, warp tile 32m x 64n
    float acc[2][8][4];
#pragma unroll
    for (int a = 0; a < 2; a++)
#pragma unroll
        for (int b = 0; b < 8; b++)
#pragma unroll
            for (int c2 = 0; c2 < 4; c2++) acc[a][b][c2] = 0.f;

    issue(0, 0);
    issue(1, 1);
    issue(2, 2);

    int st = 0;
    for (int i = 0; i < NKC; i++) {
        if (i + 1 < NKC) { CP_WAIT(2); } else { CP_WAIT(0); }
        __syncthreads();
        if (i + 3 < NKC) {
            int nst = st + 3; if (nst >= STAGES) nst -= STAGES;
            issue(i + 3, nst);
        }

        uint32_t so  = sb + st * STG_SZ;
        uint32_t AHs = so + STG_AH;
        uint32_t BHs = so + STG_BH;
        uint32_t BLs = so + STG_BL;

#pragma unroll
        for (int ks = 0; ks < 2; ks++) {
            uint32_t ah[2][4], bh[4][4], bl[4][4];
            uint32_t aoff = ks * 32 + 16 * (lane >> 4);
#pragma unroll
            for (int mt = 0; mt < 2; mt++) {
                uint32_t row = wm * 32 + mt * 16 + (lane & 15);
                ldmat_x4(ah[mt], AHs + row * A_ROWB + aoff);
            }
            uint32_t brow16 = ks * 16 + (lane & 7) + 8 * ((lane >> 3) & 1);
#pragma unroll
            for (int nh = 0; nh < 4; nh++) {
                uint32_t boff = brow16 * B_ROWB + wn * 128 + nh * 32 + 16 * (lane >> 4);
                ldmat_x4_t(bh[nh], BHs + boff);
                ldmat_x4_t(bl[nh], BLs + boff);
            }
            // hi pass: 16 independent accumulators before any reuse
#pragma unroll
            for (int mt = 0; mt < 2; mt++) {
#pragma unroll
                for (int ns = 0; ns < 8; ns++) {
                    uint32_t b0 = bh[ns >> 1][(ns & 1) * 2], b1 = bh[ns >> 1][(ns & 1) * 2 + 1];
                    mma16816(acc[mt][ns], ah[mt], b0, b1);
                }
            }
            // lo pass
#pragma unroll
            for (int mt = 0; mt < 2; mt++) {
#pragma unroll
                for (int ns = 0; ns < 8; ns++) {
                    uint32_t b0 = bl[ns >> 1][(ns & 1) * 2], b1 = bl[ns >> 1][(ns & 1) * 2 + 1];
                    mma16816(acc[mt][ns], ah[mt], b0, b1);
                }
            }
        }
        st++; if (st >= STAGES) st = 0;
    }

    // epilogue
#pragma unroll
    for (int mt = 0; mt < 2; mt++) {
#pragma unroll
        for (int half = 0; half < 2; half++) {
            int m = wm * 32 + mt * 16 + half * 8 + (lane >> 2);
            if (r0 + m < ne) {
                int   t = s_toks[m];
                float g = s_gts[m];
                float* orow = out + (size_t)t * MDIM + n0 + wn * 64 + (lane & 3) * 2;
#pragma unroll
                for (int ns = 0; ns < 8; ns++) {
                    float2 v;
                    v.x = g * acc[mt][ns][half * 2 + 0];
                    v.y = g * acc[mt][ns][half * 2 + 1];
                    *(float2*)(orow + ns * 8) = v;
                }
            }
        }
    }
}

// ---------------- launcher ----------------
extern "C" void kernel_launch(void* const* d_in, const int* in_sizes, int n_in,
                              void* d_out, int out_size) {
    const float* x  = (const float*)d_in[0];
    const float* wg = (const float*)d_in[1];
    const float* we = (const float*)d_in[2];
    float* out = (float*)d_out;

    static cudaStream_t s2 = nullptr;
    static cudaEvent_t evFork = nullptr, evJoin = nullptr;
    if (s2 == nullptr) {
        cudaStreamCreateWithFlags(&s2, cudaStreamNonBlocking);
        cudaEventCreateWithFlags(&evFork, cudaEventDisableTiming);
        cudaEventCreateWithFlags(&evJoin, cudaEventDisableTiming);
    }

    cudaEventRecord(evFork, 0);
    cudaStreamWaitEvent(s2, evFork, 0);

    cudaMemsetAsync(d_out, 0, sizeof(float) * (size_t)S * MDIM, s2);
    split_we_kernel<<<(E * MDIM * MDIM / 4) / 256, 256, 0, s2>>>(we);

    gate_kernel<<<S / 8, 256>>>(x, wg);
    scan_kernel<<<1, 256>>>(out, (long long)out_size);

    cudaEventRecord(evJoin, s2);
    cudaStreamWaitEvent(0, evJoin, 0);

    cudaFuncSetAttribute(moe_gemm_mma, cudaFuncAttributeMaxDynamicSharedMemorySize, SMEM_BYTES);
    dim3 grid(MDIM / BN, CAP / BM, E);
    moe_gemm_mma<<<grid, 256, SMEM_BYTES>>>(out);
}

// round 11
// speedup vs baseline: 1.4175x; 1.3911x over previous
#include <cuda_runtime.h>
#include <cuda_fp16.h>
#include <stdint.h>

#define S    4096
#define MDIM 1024
#define E    8
#define CAP  1024
#define BM   128
#define BN   128
#define BK   32
#define NKC  (MDIM / BK)   // 32

// ---------------- scratch (device globals; no allocation) ----------------
__device__ int    g_e0[S];
__device__ float  g_gate[S];
__device__ float  g_me_part[512 * E];
__device__ int    g_tok[E * CAP];
__device__ int    g_ne[E];
__device__ __half g_xh[S * MDIM];                 // x rounded to fp16
__device__ __half g_weh[E * MDIM * MDIM];         // we rounded to fp16, [e][k][n]

__device__ __forceinline__ uint32_t smem_u32(const void* p) {
    uint32_t a;
    asm("{ .reg .u64 t; cvta.to.shared.u64 t, %1; cvt.u32.u64 %0, t; }" : "=r"(a) : "l"(p));
    return a;
}
__device__ __forceinline__ void cp_async16(uint32_t dst, const void* src, uint32_t bytes) {
    asm volatile("cp.async.cg.shared.global [%0], [%1], 16, %2;"
                 :: "r"(dst), "l"(src), "r"(bytes) : "memory");
}
#define CP_COMMIT() asm volatile("cp.async.commit_group;" ::: "memory")
#define CP_WAIT(n)  asm volatile("cp.async.wait_group %0;" :: "n"(n) : "memory")

__device__ __forceinline__ void ldmat_x4(uint32_t* r, uint32_t addr) {
    asm volatile("ldmatrix.sync.aligned.m8n8.x4.shared.b16 {%0,%1,%2,%3}, [%4];"
                 : "=r"(r[0]), "=r"(r[1]), "=r"(r[2]), "=r"(r[3]) : "r"(addr));
}
__device__ __forceinline__ void ldmat_x4_t(uint32_t* r, uint32_t addr) {
    asm volatile("ldmatrix.sync.aligned.m8n8.x4.trans.shared.b16 {%0,%1,%2,%3}, [%4];"
                 : "=r"(r[0]), "=r"(r[1]), "=r"(r[2]), "=r"(r[3]) : "r"(addr));
}
__device__ __forceinline__ void mma16816(float* c, const uint32_t* a, uint32_t b0, uint32_t b1) {
    asm volatile("mma.sync.aligned.m16n8k16.row.col.f32.f16.f16.f32 "
                 "{%0,%1,%2,%3}, {%4,%5,%6,%7}, {%8,%9}, {%0,%1,%2,%3};"
                 : "+f"(c[0]), "+f"(c[1]), "+f"(c[2]), "+f"(c[3])
                 : "r"(a[0]), "r"(a[1]), "r"(a[2]), "r"(a[3]), "r"(b0), "r"(b1));
}

// ---------------- kernel 1: gating + fused x->fp16 + me partials ----------------
__global__ void __launch_bounds__(256) gate_kernel(const float* __restrict__ x,
                                                   const float* __restrict__ wg) {
    __shared__ float wgs[E * MDIM];
    __shared__ float s_pr[8][E];
    int tid = threadIdx.x;
    for (int i = tid; i < E * MDIM / 4; i += 256)
        ((float4*)wgs)[i] = ((const float4*)wg)[i];

    int warp = tid >> 5, lane = tid & 31;
    int s = blockIdx.x * 8 + warp;
    const float4* xr = (const float4*)(x + (size_t)s * MDIM);

    float4 xv[8];
#pragma unroll
    for (int it = 0; it < 8; it++) xv[it] = xr[it * 32 + lane];

    __half2* xh = (__half2*)(g_xh + (size_t)s * MDIM);
#pragma unroll
    for (int it = 0; it < 8; it++) {
        int k4 = it * 32 + lane;
        xh[k4 * 2 + 0] = __halves2half2(__float2half_rn(xv[it].x), __float2half_rn(xv[it].y));
        xh[k4 * 2 + 1] = __halves2half2(__float2half_rn(xv[it].z), __float2half_rn(xv[it].w));
    }
    __syncthreads();

    float acc[E];
#pragma unroll
    for (int e = 0; e < E; e++) acc[e] = 0.f;
#pragma unroll
    for (int it = 0; it < 8; it++) {
        int k4 = it * 32 + lane;
#pragma unroll
        for (int e = 0; e < E; e++) {
            float4 wv = ((const float4*)(wgs + e * MDIM))[k4];
            acc[e] += xv[it].x * wv.x + xv[it].y * wv.y + xv[it].z * wv.z + xv[it].w * wv.w;
        }
    }
#pragma unroll
    for (int e = 0; e < E; e++) {
#pragma unroll
        for (int off = 16; off; off >>= 1)
            acc[e] += __shfl_xor_sync(0xffffffffu, acc[e], off);
    }
    if (lane == 0) {
        float mx = acc[0]; int ei = 0;
#pragma unroll
        for (int e = 1; e < E; e++) if (acc[e] > mx) { mx = acc[e]; ei = e; }
        float ex[E]; float sum = 0.f;
#pragma unroll
        for (int e = 0; e < E; e++) { ex[e] = expf(acc[e] - mx); sum += ex[e]; }
        float inv = 1.f / sum;
#pragma unroll
        for (int e = 0; e < E; e++) s_pr[warp][e] = ex[e] * inv;
        g_e0[s]   = ei;
        g_gate[s] = ex[ei] * inv;
    }
    __syncthreads();
    if (tid < E) {
        float m = 0.f;
#pragma unroll
        for (int w = 0; w < 8; w++) m += s_pr[w][tid];
        g_me_part[blockIdx.x * E + tid] = m;
    }
}

// ---------------- kernel 2: ordered prefix scan + loss ----------------
__global__ void __launch_bounds__(256) scan_kernel(float* __restrict__ d_out,
                                                   long long out_size) {
    const int T = 256, CH = S / T;  // 16
    __shared__ int   cnt[T][E];
    __shared__ float s_me[32][E];
    __shared__ int   tot[E];
    int tid = threadIdx.x;

    int e0l[CH];
    {
        const int4* p = (const int4*)(g_e0 + tid * CH);
#pragma unroll
        for (int q = 0; q < CH / 4; q++) {
            int4 v = p[q];
            e0l[q * 4 + 0] = v.x; e0l[q * 4 + 1] = v.y;
            e0l[q * 4 + 2] = v.z; e0l[q * 4 + 3] = v.w;
        }
    }
    int c[E];
#pragma unroll
    for (int e = 0; e < E; e++) c[e] = 0;
#pragma unroll
    for (int i = 0; i < CH; i++) c[e0l[i]]++;
#pragma unroll
    for (int e = 0; e < E; e++) cnt[tid][e] = c[e];

    {
        int e = tid & 7, grp = tid >> 3;
        float m = 0.f;
#pragma unroll
        for (int j = 0; j < 16; j++) m += g_me_part[(grp * 16 + j) * E + e];
        s_me[grp][e] = m;
    }
    __syncthreads();
    for (int stride = 16; stride; stride >>= 1) {
        if (tid < stride * E) {
            int e = tid & 7, grp = tid >> 3;
            s_me[grp][e] += s_me[grp + stride][e];
        }
        __syncthreads();
    }

    if (tid < E) {
        int run = 0;
        for (int t = 0; t < T; t++) { int v = cnt[t][tid]; cnt[t][tid] = run; run += v; }
        tot[tid] = run;
        g_ne[tid] = run < CAP ? run : CAP;
    }
    __syncthreads();
    int off[E];
#pragma unroll
    for (int e = 0; e < E; e++) off[e] = cnt[tid][e];
    int base_s = tid * CH;
#pragma unroll
    for (int i = 0; i < CH; i++) {
        int e = e0l[i];
        int loc = off[e]++;
        if (loc < CAP) g_tok[e * CAP + loc] = base_s + i;
    }
    if (tid == 0 && out_size > (long long)S * MDIM) {
        float loss = 0.f;
#pragma unroll
        for (int e = 0; e < E; e++) loss += s_me[0][e] * (float)tot[e];
        loss *= (float)E / ((float)S * (float)S);
        d_out[(long long)S * MDIM] = loss;
    }
}

// ---------------- prep: we fp32 -> fp16 (single plane) ----------------
__global__ void __launch_bounds__(256) round_we_kernel(const float* __restrict__ we) {
    size_t i = (size_t)blockIdx.x * 256 + threadIdx.x;
    float4 v = ((const float4*)we)[i];
    __half2* oh = (__half2*)g_weh + i * 2;
    oh[0] = __halves2half2(__float2half_rn(v.x), __float2half_rn(v.y));
    oh[1] = __halves2half2(__float2half_rn(v.z), __float2half_rn(v.w));
}

// ---------------- kernel 3: grouped GEMM, 128x128x32, single-fp16, 2 CTA/SM ----------------
#define A_ROWB 80
#define B_ROWB 272
#define A_TILE (BM * A_ROWB)            // 10240
#define B_TILE (BK * B_ROWB)            // 8704
#define STG_AH 0
#define STG_BH (A_TILE)
#define STG_SZ (A_TILE + B_TILE)        // 18944
#define STAGES 4
#define SMEM_BYTES (STAGES * STG_SZ)    // 75776

__global__ void __launch_bounds__(256, 2) moe_gemm_mma(float* __restrict__ out) {
    int e  = blockIdx.z;
    int ne = g_ne[e];
    int r0 = blockIdx.y * BM;
    if (r0 >= ne) return;
    int n0 = blockIdx.x * BN;

    extern __shared__ __align__(16) char sm[];
    uint32_t sb = smem_u32(sm);
    __shared__ int   s_toks[BM];
    __shared__ float s_gts[BM];

    int tid = threadIdx.x;
    int wid = tid >> 5, lane = tid & 31;

    if (tid < BM) {
        int r = r0 + tid;
        int t = (r < ne) ? g_tok[e * CAP + r] : -1;
        s_toks[tid] = t;
        s_gts[tid]  = (t >= 0) ? g_gate[t] : 0.f;
    }
    __syncthreads();

    // A load: 128 rows x 64B; thread -> (row=tid>>1, 2 chunks of 16B)
    int arow = tid >> 1, aseg = tid & 1;
    int atok = s_toks[arow];
    const char* axh = (const char*)(g_xh + ((atok >= 0 ? (size_t)atok : 0) * MDIM)) + aseg * 32;
    uint32_t abytes = (atok >= 0) ? 16u : 0u;
    uint32_t adst = arow * A_ROWB + aseg * 32;

    // B load: 32 rows x 256B; thread -> (row=tid>>3, 2 chunks 128B apart)
    int brow = tid >> 3, bc = tid & 7;
    const char* bwh = (const char*)(g_weh + ((size_t)e << 20) + (size_t)brow * MDIM + n0) + bc * 16;
    uint32_t bdst = brow * B_ROWB + bc * 16;
    const size_t bkstep = (size_t)BK * MDIM * 2;

    auto issue = [&](int kc, int st) {
        uint32_t so = sb + st * STG_SZ;
        size_t akoff = (size_t)kc * BK * 2;
        cp_async16(so + STG_AH + adst,      axh + akoff,      abytes);
        cp_async16(so + STG_AH + adst + 16, axh + akoff + 16, abytes);
        size_t bko = (size_t)kc * bkstep;
#pragma unroll
        for (int j = 0; j < 2; j++)
            cp_async16(so + STG_BH + bdst + j * 128, bwh + bko + j * 128, 16u);
        CP_COMMIT();
    };

    int wm = wid & 3, wn = wid >> 2;   // 8 warps: 4m x 2n, warp tile 32m x 64n
    float acc[2][8][4];
#pragma unroll
    for (int a = 0; a < 2; a++)
#pragma unroll
        for (int b = 0; b < 8; b++)
#pragma unroll
            for (int c2 = 0; c2 < 4; c2++) acc[a][b][c2] = 0.f;

    issue(0, 0);
    issue(1, 1);
    issue(2, 2);

    int st = 0;
    for (int i = 0; i < NKC; i++) {
        if (i + 1 < NKC) { CP_WAIT(2); } else { CP_WAIT(0); }
        __syncthreads();
        if (i + 3 < NKC) {
            int nst = st + 3; if (nst >= STAGES) nst -= STAGES;
            issue(i + 3, nst);
        }

        uint32_t so  = sb + st * STG_SZ;
        uint32_t AHs = so + STG_AH;
        uint32_t BHs = so + STG_BH;

#pragma unroll
        for (int ks = 0; ks < 2; ks++) {
            uint32_t ah[2][4], bh[4][4];
            uint32_t aoff = ks * 32 + 16 * (lane >> 4);
#pragma unroll
            for (int mt = 0; mt < 2; mt++) {
                uint32_t row = wm * 32 + mt * 16 + (lane & 15);
                ldmat_x4(ah[mt], AHs + row * A_ROWB + aoff);
            }
            uint32_t brow16 = ks * 16 + (lane & 7) + 8 * ((lane >> 3) & 1);
#pragma unroll
            for (int nh = 0; nh < 4; nh++) {
                uint32_t boff = brow16 * B_ROWB + wn * 128 + nh * 32 + 16 * (lane >> 4);
                ldmat_x4_t(bh[nh], BHs + boff);
            }
#pragma unroll
            for (int mt = 0; mt < 2; mt++) {
#pragma unroll
                for (int ns = 0; ns < 8; ns++) {
                    uint32_t b0 = bh[ns >> 1][(ns & 1) * 2], b1 = bh[ns >> 1][(ns & 1) * 2 + 1];
                    mma16816(acc[mt][ns], ah[mt], b0, b1);
                }
            }
        }
        st++; if (st >= STAGES) st = 0;
    }

    // epilogue
#pragma unroll
    for (int mt = 0; mt < 2; mt++) {
#pragma unroll
        for (int half = 0; half < 2; half++) {
            int m = wm * 32 + mt * 16 + half * 8 + (lane >> 2);
            if (r0 + m < ne) {
                int   t = s_toks[m];
                float g = s_gts[m];
                float* orow = out + (size_t)t * MDIM + n0 + wn * 64 + (lane & 3) * 2;
#pragma unroll
                for (int ns = 0; ns < 8; ns++) {
                    float2 v;
                    v.x = g * acc[mt][ns][half * 2 + 0];
                    v.y = g * acc[mt][ns][half * 2 + 1];
                    *(float2*)(orow + ns * 8) = v;
                }
            }
        }
    }
}

// ---------------- launcher ----------------
extern "C" void kernel_launch(void* const* d_in, const int* in_sizes, int n_in,
                              void* d_out, int out_size) {
    const float* x  = (const float*)d_in[0];
    const float* wg = (const float*)d_in[1];
    const float* we = (const float*)d_in[2];
    float* out = (float*)d_out;

    static cudaStream_t s2 = nullptr;
    static cudaEvent_t evFork = nullptr, evJoin = nullptr;
    if (s2 == nullptr) {
        cudaStreamCreateWithFlags(&s2, cudaStreamNonBlocking);
        cudaEventCreateWithFlags(&evFork, cudaEventDisableTiming);
        cudaEventCreateWithFlags(&evJoin, cudaEventDisableTiming);
    }

    cudaEventRecord(evFork, 0);
    cudaStreamWaitEvent(s2, evFork, 0);

    cudaMemsetAsync(d_out, 0, sizeof(float) * (size_t)S * MDIM, s2);
    round_we_kernel<<<(E * MDIM * MDIM / 4) / 256, 256, 0, s2>>>(we);

    gate_kernel<<<S / 8, 256>>>(x, wg);
    scan_kernel<<<1, 256>>>(out, (long long)out_size);

    cudaEventRecord(evJoin, s2);
    cudaStreamWaitEvent(0, evJoin, 0);

    cudaFuncSetAttribute(moe_gemm_mma, cudaFuncAttributeMaxDynamicSharedMemorySize, SMEM_BYTES);
    dim3 grid(MDIM / BN, CAP / BM, E);
    moe_gemm_mma<<<grid, 256, SMEM_BYTES>>>(out);
}